// round 12
// baseline (speedup 1.0000x reference)
#include <cuda_runtime.h>

// Problem constants
#define BB 128
#define JJ 17
#define YY 96
#define XX 72
#define YX (YY * XX)                 // 6912
#define NTOT (BB * JJ * YX)          // 15,040,512 elements per plane
#define N4 (NTOT / 4)                // 3,760,128 float4 chunks per plane

#define NBLK 1184                    // 148 SMs * 8 blocks (2048 thr/SM, one wave)
#define NTHR 256

static __device__ float        g_acc   = 0.0f;  // self-resets via atom.exch
static __device__ unsigned int g_count = 0;     // self-resets via atom.inc wrap

__global__ void __launch_bounds__(NTHR) regloss_reduce(
    const float* __restrict__ loc,
    const float* __restrict__ cord,
    const float* __restrict__ tw,
    float* __restrict__ out)
{
    const float4* __restrict__ loc0 = reinterpret_cast<const float4*>(loc);
    const float4* __restrict__ loc1 = reinterpret_cast<const float4*>(loc + NTOT);

    float acc = 0.0f;
    const int stride = gridDim.x * blockDim.x;
    for (int i = blockIdx.x * blockDim.x + threadIdx.x; i < N4; i += stride) {
        const int n  = i * 4;
        const int m  = n / YX;            // = b*J + j (same flat index for tw AND cord)
        const int p  = n - m * YX;
        const int y  = p / XX;
        const int x0 = p - y * XX;

        const float w  = __ldg(tw + m);
        const float cx = __ldg(cord + m);            // cord[0] flat index == m
        const float cy = __ldg(cord + JJ * BB + m);  // cord[1]

        const float4 lx = __ldg(loc0 + i);
        const float4 ly = __ldg(loc1 + i);

        // int32-truncated ground-truth shifts (toward zero, matches astype(int32))
        const float gy  = truncf((float)y - cy);
        const float gx0 = truncf((float)(x0 + 0) - cx);
        const float gx1 = truncf((float)(x0 + 1) - cx);
        const float gx2 = truncf((float)(x0 + 2) - cx);
        const float gx3 = truncf((float)(x0 + 3) - cx);

        float d;
        d = (lx.x - gx0) * w; acc = fmaf(d, d, acc);
        d = (lx.y - gx1) * w; acc = fmaf(d, d, acc);
        d = (lx.z - gx2) * w; acc = fmaf(d, d, acc);
        d = (lx.w - gx3) * w; acc = fmaf(d, d, acc);
        d = (ly.x - gy)  * w; acc = fmaf(d, d, acc);
        d = (ly.y - gy)  * w; acc = fmaf(d, d, acc);
        d = (ly.z - gy)  * w; acc = fmaf(d, d, acc);
        d = (ly.w - gy)  * w; acc = fmaf(d, d, acc);
    }

    // ── Block tree reduction (deterministic within block) ──
    __shared__ float sm[NTHR];
    sm[threadIdx.x] = acc;
    __syncthreads();
    #pragma unroll
    for (int s = NTHR / 2; s >= 32; s >>= 1) {
        if (threadIdx.x < s) sm[threadIdx.x] += sm[threadIdx.x + s];
        __syncthreads();
    }
    if (threadIdx.x < 32) {
        float v = sm[threadIdx.x];
        #pragma unroll
        for (int off = 16; off > 0; off >>= 1)
            v += __shfl_down_sync(0xFFFFFFFFu, v, off);
        if (threadIdx.x == 0) {
            // Scaled block partial into global accumulator.
            const double scale = 0.5 / (double)NTOT;
            const float contrib = (float)((double)v * scale);

            float* accp = &g_acc;
            unsigned int* cntp = &g_count;

            // release-add: no fence, no L1 flush (unlike __threadfence)
            asm volatile("red.release.gpu.add.f32 [%0], %1;"
                         :: "l"(accp), "f"(contrib) : "memory");
            // release-inc orders this block's add before the count bump;
            // wraps NBLK-1 -> 0, self-resetting for the next graph replay.
            unsigned int old;
            asm volatile("atom.release.gpu.inc.u32 %0, [%1], %2;"
                         : "=r"(old) : "l"(cntp), "r"(NBLK - 1u) : "memory");
            if (old == NBLK - 1u) {
                // acquire-exchange: returns the complete sum (every add is
                // ordered before its inc; acquire syncs with all of them)
                // and resets the accumulator to 0 for the next replay.
                unsigned int bits;
                asm volatile("atom.acquire.gpu.exch.b32 %0, [%1], %2;"
                             : "=r"(bits) : "l"(accp), "r"(0u) : "memory");
                out[0] = __uint_as_float(bits);
            }
        }
    }
}

extern "C" void kernel_launch(void* const* d_in, const int* in_sizes, int n_in,
                              void* d_out, int out_size)
{
    const float* loc  = (const float*)d_in[0];   // (2, B, J, Y, X) fp32
    const float* cord = (const float*)d_in[1];   // (2, J, B) fp32
    const float* tw   = (const float*)d_in[2];   // (B, J, 1) fp32
    float* out = (float*)d_out;

    regloss_reduce<<<NBLK, NTHR>>>(loc, cord, tw, out);
}